// round 5
// baseline (speedup 1.0000x reference)
#include <cuda_runtime.h>
#include <cuda_bf16.h>
#include <math.h>

#define BATCH 2
#define SEQ   2048
#define NEMBD 1024
#define NHEAD 16
#define HSZ   64
#define FFDIM 4096
#define BT    (BATCH*SEQ)      // 4096 rows
#define LN_EPS 1e-5f

// ---------------- scratch (device globals; no allocation allowed) ----------------
__device__ float g_h[(size_t)BT*NEMBD];
__device__ float g_q[(size_t)BT*NEMBD];
__device__ float g_k[(size_t)BT*NEMBD];
__device__ float g_v[(size_t)BT*NEMBD];
__device__ float g_attn[(size_t)BT*NEMBD];
__device__ float g_x2[(size_t)BT*NEMBD];
__device__ float g_f1[(size_t)BT*FFDIM];
__device__ float g_scores[(size_t)BATCH*NHEAD*SEQ*SEQ];   // 512 MB

// ---------------- LayerNorm: one block per row, 256 threads, C=1024 ----------------
__global__ void ln_kernel(const float* __restrict__ x, const float* __restrict__ w,
                          const float* __restrict__ b, float* __restrict__ out)
{
    int row = blockIdx.x;
    const float4* xr = (const float4*)(x + (size_t)row*NEMBD);
    int t = threadIdx.x;                 // 256 threads * float4 = 1024
    float4 v = xr[t];
    float s  = v.x + v.y + v.z + v.w;
    float s2 = v.x*v.x + v.y*v.y + v.z*v.z + v.w*v.w;
    #pragma unroll
    for (int o = 16; o > 0; o >>= 1) {
        s  += __shfl_xor_sync(0xffffffffu, s,  o);
        s2 += __shfl_xor_sync(0xffffffffu, s2, o);
    }
    __shared__ float ss[8], ss2[8];
    int wid = t >> 5, lid = t & 31;
    if (lid == 0) { ss[wid] = s; ss2[wid] = s2; }
    __syncthreads();
    if (wid == 0) {
        float a  = (lid < 8) ? ss[lid]  : 0.f;
        float a2 = (lid < 8) ? ss2[lid] : 0.f;
        #pragma unroll
        for (int o = 4; o > 0; o >>= 1) {
            a  += __shfl_xor_sync(0xffffffffu, a,  o);
            a2 += __shfl_xor_sync(0xffffffffu, a2, o);
        }
        if (lid == 0) { ss[0] = a; ss2[0] = a2; }
    }
    __syncthreads();
    float mu  = ss[0]  * (1.0f/NEMBD);
    float var = ss2[0] * (1.0f/NEMBD) - mu*mu;
    float inv = rsqrtf(var + LN_EPS);
    const float4 wv = ((const float4*)w)[t];
    const float4 bv = ((const float4*)b)[t];
    float4 o4;
    o4.x = (v.x - mu)*inv*wv.x + bv.x;
    o4.y = (v.y - mu)*inv*wv.y + bv.y;
    o4.z = (v.z - mu)*inv*wv.z + bv.z;
    o4.w = (v.w - mu)*inv*wv.w + bv.w;
    ((float4*)(out + (size_t)row*NEMBD))[t] = o4;
}

// ---------------- generic tiled SGEMM (fp32 SIMT) ----------------
// C[m,n] = alpha * sum_k A[m,k]*B[k,n]  (+bias[n]) (relu) (+res[m,n]) ; batched via z
template<int BM,int BN,int BK,int TM,int TN>
__global__ void __launch_bounds__((BM/TM)*(BN/TN))
gemm_k(const float* __restrict__ A, const float* __restrict__ Bm,
       const float* __restrict__ bias, const float* __restrict__ res,
       float* __restrict__ C,
       int M, int N, int K, int lda, int ldb, int ldc,
       long long sAb, long long sAh, long long sBb, long long sBh,
       long long sCb, long long sCh, int Hdim,
       float alpha, int relu)
{
    constexpr int THREADS = (BM/TM)*(BN/TN);
    int z = blockIdx.z;
    int bb = z / Hdim, hh = z % Hdim;
    A  += bb*sAb + hh*sAh;
    Bm += bb*sBb + hh*sBh;
    C  += bb*sCb + hh*sCh;
    if (res) res += bb*sCb + hh*sCh;

    __shared__ float As[BK][BM];
    __shared__ float Bs[BK][BN];

    int tid  = threadIdx.x;
    int row0 = blockIdx.y * BM;
    int col0 = blockIdx.x * BN;

    constexpr int A_F4 = BK/4;
    int aRow = tid / A_F4;
    int aCol = (tid % A_F4)*4;
    constexpr int A_RS = THREADS / A_F4;
    constexpr int B_F4 = BN/4;
    int bRow = tid / B_F4;
    int bCol = (tid % B_F4)*4;
    constexpr int B_RS = THREADS / B_F4;

    int ty = tid / (BN/TN);
    int tx = tid % (BN/TN);

    float acc[TM][TN];
    #pragma unroll
    for (int i=0;i<TM;i++)
        #pragma unroll
        for (int j=0;j<TN;j++) acc[i][j] = 0.f;

    for (int k0 = 0; k0 < K; k0 += BK) {
        #pragma unroll
        for (int r = aRow; r < BM; r += A_RS) {
            float4 v = *(const float4*)(A + (long long)(row0 + r)*lda + k0 + aCol);
            As[aCol+0][r] = v.x; As[aCol+1][r] = v.y;
            As[aCol+2][r] = v.z; As[aCol+3][r] = v.w;
        }
        #pragma unroll
        for (int r = bRow; r < BK; r += B_RS) {
            *(float4*)(&Bs[r][bCol]) =
                *(const float4*)(Bm + (long long)(k0 + r)*ldb + col0 + bCol);
        }
        __syncthreads();
        #pragma unroll
        for (int kk = 0; kk < BK; kk++) {
            float ra[TM], rb[TN];
            #pragma unroll
            for (int i=0;i<TM;i+=4) {
                float4 v = *(const float4*)(&As[kk][ty*TM+i]);
                ra[i]=v.x; ra[i+1]=v.y; ra[i+2]=v.z; ra[i+3]=v.w;
            }
            #pragma unroll
            for (int j=0;j<TN;j+=4) {
                float4 v = *(const float4*)(&Bs[kk][tx*TN+j]);
                rb[j]=v.x; rb[j+1]=v.y; rb[j+2]=v.z; rb[j+3]=v.w;
            }
            #pragma unroll
            for (int i=0;i<TM;i++)
                #pragma unroll
                for (int j=0;j<TN;j++)
                    acc[i][j] = fmaf(ra[i], rb[j], acc[i][j]);
        }
        __syncthreads();
    }
    #pragma unroll
    for (int i=0;i<TM;i++) {
        int r = row0 + ty*TM + i;
        #pragma unroll
        for (int j=0;j<TN;j++) {
            int c = col0 + tx*TN + j;
            float v = acc[i][j] * alpha;
            if (bias) v += bias[c];
            if (relu) v = fmaxf(v, 0.f);
            if (res)  v += res[(long long)r*ldc + c];
            C[(long long)r*ldc + c] = v;
        }
    }
}

// ---------------- attention scores: S[bh, t, s] = scale * q_t . k_s (causal) ----------------
__global__ void __launch_bounds__(256)
scores_kernel(const float* __restrict__ q, const float* __restrict__ k,
              float* __restrict__ scores)
{
    int si = blockIdx.x, ti = blockIdx.y, bh = blockIdx.z;
    if (si > ti) return;                    // fully masked tile, never read later
    int b = bh / NHEAD, h = bh % NHEAD;
    const float* Q  = q + (long long)b*SEQ*NEMBD + h*HSZ;
    const float* Kp = k + (long long)b*SEQ*NEMBD + h*HSZ;

    __shared__ float Qs[HSZ][65];   // [d][row], padded
    __shared__ float Ks[HSZ][65];

    int tid = threadIdx.x;
    for (int i = tid; i < 64*16; i += 256) {
        int r = i >> 4, c4 = (i & 15) << 2;
        float4 vq = *(const float4*)(Q  + (long long)(ti*64 + r)*NEMBD + c4);
        Qs[c4+0][r]=vq.x; Qs[c4+1][r]=vq.y; Qs[c4+2][r]=vq.z; Qs[c4+3][r]=vq.w;
        float4 vk = *(const float4*)(Kp + (long long)(si*64 + r)*NEMBD + c4);
        Ks[c4+0][r]=vk.x; Ks[c4+1][r]=vk.y; Ks[c4+2][r]=vk.z; Ks[c4+3][r]=vk.w;
    }
    __syncthreads();

    int ty = tid / 16, tx = tid % 16;
    float acc[4][4];
    #pragma unroll
    for (int i=0;i<4;i++) { acc[i][0]=0.f; acc[i][1]=0.f; acc[i][2]=0.f; acc[i][3]=0.f; }

    #pragma unroll
    for (int kk = 0; kk < HSZ; kk++) {
        float ra[4], rb[4];
        #pragma unroll
        for (int i=0;i<4;i++) ra[i] = Qs[kk][ty*4+i];
        #pragma unroll
        for (int j=0;j<4;j++) rb[j] = Ks[kk][tx*4+j];
        #pragma unroll
        for (int i=0;i<4;i++)
            #pragma unroll
            for (int j=0;j<4;j++) acc[i][j] = fmaf(ra[i], rb[j], acc[i][j]);
    }

    const float scale = 0.03125f;          // 1024^-0.5
    float* S = scores + (long long)bh*SEQ*SEQ;
    #pragma unroll
    for (int i=0;i<4;i++) {
        int tt = ti*64 + ty*4 + i;
        #pragma unroll
        for (int j=0;j<4;j++) {
            int ss = si*64 + tx*4 + j;
            S[(long long)tt*SEQ + ss] = (ss <= tt) ? acc[i][j]*scale : -INFINITY;
        }
    }
}

// ---------------- causal softmax, in-place; zeros above diagonal ----------------
__global__ void __launch_bounds__(256)
softmax_kernel(float* __restrict__ scores)
{
    long long row = blockIdx.x;                 // B*H*SEQ rows
    int t   = (int)(row % SEQ);
    int len = t + 1;
    float* p = scores + row * (long long)SEQ;
    int tid = threadIdx.x;

    float m = -INFINITY;
    for (int i = tid; i < len; i += 256) m = fmaxf(m, p[i]);
    #pragma unroll
    for (int o=16;o>0;o>>=1) m = fmaxf(m, __shfl_xor_sync(0xffffffffu, m, o));
    __shared__ float sm[8];
    int wid = tid >> 5, lid = tid & 31;
    if (lid == 0) sm[wid] = m;
    __syncthreads();
    if (wid == 0) {
        float a = (lid < 8) ? sm[lid] : -INFINITY;
        #pragma unroll
        for (int o=4;o>0;o>>=1) a = fmaxf(a, __shfl_xor_sync(0xffffffffu, a, o));
        if (lid == 0) sm[0] = a;
    }
    __syncthreads();
    m = sm[0];

    float s = 0.f;
    for (int i = tid; i < len; i += 256) s += __expf(p[i] - m);
    #pragma unroll
    for (int o=16;o>0;o>>=1) s += __shfl_xor_sync(0xffffffffu, s, o);
    __shared__ float ssum[8];
    if (lid == 0) ssum[wid] = s;
    __syncthreads();
    if (wid == 0) {
        float a = (lid < 8) ? ssum[lid] : 0.f;
        #pragma unroll
        for (int o=4;o>0;o>>=1) a += __shfl_xor_sync(0xffffffffu, a, o);
        if (lid == 0) ssum[0] = a;
    }
    __syncthreads();
    float inv = 1.0f / ssum[0];

    for (int i = tid; i < SEQ; i += 256)
        p[i] = (i < len) ? __expf(p[i] - m) * inv : 0.f;
}

// ---------------- launch ----------------
extern "C" void kernel_launch(void* const* d_in, const int* in_sizes, int n_in,
                              void* d_out, int out_size)
{
    const float* x     = (const float*)d_in[0];
    const float* Wq    = (const float*)d_in[1];
    const float* Wk    = (const float*)d_in[2];
    const float* Wv    = (const float*)d_in[3];
    const float* Wproj = (const float*)d_in[4];
    const float* bproj = (const float*)d_in[5];
    const float* W1    = (const float*)d_in[6];
    const float* b1    = (const float*)d_in[7];
    const float* W2    = (const float*)d_in[8];
    const float* b2    = (const float*)d_in[9];
    const float* ln1w  = (const float*)d_in[10];
    const float* ln1b  = (const float*)d_in[11];
    const float* ln2w  = (const float*)d_in[12];
    const float* ln2b  = (const float*)d_in[13];
    float* out = (float*)d_out;

    float *ph, *pq, *pk, *pv, *pattn, *px2, *pf1, *pscores;
    cudaGetSymbolAddress((void**)&ph,     g_h);
    cudaGetSymbolAddress((void**)&pq,     g_q);
    cudaGetSymbolAddress((void**)&pk,     g_k);
    cudaGetSymbolAddress((void**)&pv,     g_v);
    cudaGetSymbolAddress((void**)&pattn,  g_attn);
    cudaGetSymbolAddress((void**)&px2,    g_x2);
    cudaGetSymbolAddress((void**)&pf1,    g_f1);
    cudaGetSymbolAddress((void**)&pscores,g_scores);

    const long long Z = 0;

    // 1) LN1
    ln_kernel<<<BT, 256>>>(x, ln1w, ln1b, ph);

    // 2) Q,K,V projections  (M=4096,N=1024,K=1024)
    {
        dim3 grid(NEMBD/128, BT/128, 1);
        gemm_k<128,128,16,8,8><<<grid, 256>>>(ph, Wq, nullptr, nullptr, pq,
            BT, NEMBD, NEMBD, NEMBD, NEMBD, NEMBD, Z,Z,Z,Z,Z,Z, 1, 1.0f, 0);
        gemm_k<128,128,16,8,8><<<grid, 256>>>(ph, Wk, nullptr, nullptr, pk,
            BT, NEMBD, NEMBD, NEMBD, NEMBD, NEMBD, Z,Z,Z,Z,Z,Z, 1, 1.0f, 0);
        gemm_k<128,128,16,8,8><<<grid, 256>>>(ph, Wv, nullptr, nullptr, pv,
            BT, NEMBD, NEMBD, NEMBD, NEMBD, NEMBD, Z,Z,Z,Z,Z,Z, 1, 1.0f, 0);
    }

    // 3) causal scores
    {
        dim3 grid(SEQ/64, SEQ/64, BATCH*NHEAD);
        scores_kernel<<<grid, 256>>>(pq, pk, pscores);
    }

    // 4) softmax (writes zeros above diagonal)
    softmax_kernel<<<BATCH*NHEAD*SEQ, 256>>>(pscores);

    // 5) attn = P @ V   (per (b,h): M=2048,N=64,K=2048)
    {
        dim3 grid(1, SEQ/128, BATCH*NHEAD);
        gemm_k<128,64,16,8,4><<<grid, 256>>>(pscores, pv, nullptr, nullptr, pattn,
            SEQ, HSZ, SEQ, SEQ, NEMBD, NEMBD,
            (long long)NHEAD*SEQ*SEQ, (long long)SEQ*SEQ,
            (long long)SEQ*NEMBD, (long long)HSZ,
            (long long)SEQ*NEMBD, (long long)HSZ,
            NHEAD, 1.0f, 0);
    }

    // 6) x2 = x + attn @ Wproj + bproj
    {
        dim3 grid(NEMBD/128, BT/128, 1);
        gemm_k<128,128,16,8,8><<<grid, 256>>>(pattn, Wproj, bproj, x, px2,
            BT, NEMBD, NEMBD, NEMBD, NEMBD, NEMBD, Z,Z,Z,Z,Z,Z, 1, 1.0f, 0);
    }

    // 7) LN2
    ln_kernel<<<BT, 256>>>(px2, ln2w, ln2b, ph);

    // 8) f1 = relu(h2 @ W1 + b1)   (M=4096,N=4096,K=1024)  -- relu=1 (was the bug!)
    {
        dim3 grid(FFDIM/128, BT/128, 1);
        gemm_k<128,128,16,8,8><<<grid, 256>>>(ph, W1, b1, nullptr, pf1,
            BT, FFDIM, NEMBD, NEMBD, FFDIM, FFDIM, Z,Z,Z,Z,Z,Z, 1, 1.0f, 1);
    }

    // 9) out = x2 + f1 @ W2 + b2   (M=4096,N=1024,K=4096)
    {
        dim3 grid(NEMBD/128, BT/128, 1);
        gemm_k<128,128,16,8,8><<<grid, 256>>>(pf1, W2, b2, px2, out,
            BT, NEMBD, FFDIM, FFDIM, NEMBD, NEMBD, Z,Z,Z,Z,Z,Z, 1, 1.0f, 0);
    }
}

// round 6
// speedup vs baseline: 2.0836x; 2.0836x over previous
#include <cuda_runtime.h>
#include <cuda_bf16.h>
#include <math.h>
#include <stdint.h>

#define BATCH 2
#define SEQ   2048
#define NEMBD 1024
#define NHEAD 16
#define HSZ   64
#define FFDIM 4096
#define BT    (BATCH*SEQ)      // 4096 rows
#define LN_EPS 1e-5f

// ---------------- scratch (device globals; no allocation allowed) ----------------
__device__ float g_h[(size_t)BT*NEMBD];
__device__ float g_q[(size_t)BT*NEMBD];
__device__ float g_k[(size_t)BT*NEMBD];
__device__ float g_v[(size_t)BT*NEMBD];
__device__ float g_attn[(size_t)BT*NEMBD];
__device__ float g_x2[(size_t)BT*NEMBD];
__device__ float g_f1[(size_t)BT*FFDIM];
__device__ float g_scores[(size_t)BATCH*NHEAD*SEQ*SEQ];   // 512 MB

// ---------------- helpers ----------------
__device__ __forceinline__ uint32_t f2tf32(float x) {
    uint32_t r;
    asm("cvt.rna.tf32.f32 %0, %1;" : "=r"(r) : "f"(x));
    return r;
}

__device__ __forceinline__ void mma_tf32(float* c, const uint32_t* a, const uint32_t* b) {
    asm volatile(
        "mma.sync.aligned.m16n8k8.row.col.f32.tf32.tf32.f32 "
        "{%0,%1,%2,%3}, {%4,%5,%6,%7}, {%8,%9}, {%0,%1,%2,%3};"
        : "+f"(c[0]), "+f"(c[1]), "+f"(c[2]), "+f"(c[3])
        : "r"(a[0]), "r"(a[1]), "r"(a[2]), "r"(a[3]), "r"(b[0]), "r"(b[1]));
}

// ---------------- LayerNorm: one block per row, 256 threads, C=1024 ----------------
__global__ void ln_kernel(const float* __restrict__ x, const float* __restrict__ w,
                          const float* __restrict__ b, float* __restrict__ out)
{
    int row = blockIdx.x;
    const float4* xr = (const float4*)(x + (size_t)row*NEMBD);
    int t = threadIdx.x;
    float4 v = xr[t];
    float s  = v.x + v.y + v.z + v.w;
    float s2 = v.x*v.x + v.y*v.y + v.z*v.z + v.w*v.w;
    #pragma unroll
    for (int o = 16; o > 0; o >>= 1) {
        s  += __shfl_xor_sync(0xffffffffu, s,  o);
        s2 += __shfl_xor_sync(0xffffffffu, s2, o);
    }
    __shared__ float ss[8], ss2[8];
    int wid = t >> 5, lid = t & 31;
    if (lid == 0) { ss[wid] = s; ss2[wid] = s2; }
    __syncthreads();
    if (wid == 0) {
        float a  = (lid < 8) ? ss[lid]  : 0.f;
        float a2 = (lid < 8) ? ss2[lid] : 0.f;
        #pragma unroll
        for (int o = 4; o > 0; o >>= 1) {
            a  += __shfl_xor_sync(0xffffffffu, a,  o);
            a2 += __shfl_xor_sync(0xffffffffu, a2, o);
        }
        if (lid == 0) { ss[0] = a; ss2[0] = a2; }
    }
    __syncthreads();
    float mu  = ss[0]  * (1.0f/NEMBD);
    float var = ss2[0] * (1.0f/NEMBD) - mu*mu;
    float inv = rsqrtf(var + LN_EPS);
    const float4 wv = ((const float4*)w)[t];
    const float4 bv = ((const float4*)b)[t];
    float4 o4;
    o4.x = (v.x - mu)*inv*wv.x + bv.x;
    o4.y = (v.y - mu)*inv*wv.y + bv.y;
    o4.z = (v.z - mu)*inv*wv.z + bv.z;
    o4.w = (v.w - mu)*inv*wv.w + bv.w;
    ((float4*)(out + (size_t)row*NEMBD))[t] = o4;
}

// ---------------- tf32 tensor-core GEMM ----------------
// C[m,n] = alpha * sum_k A[m,k]*B[k,n]  (+bias[n]) (relu) (+res[m,n]); batched via z.
// A row-major [M,K] lda, B row-major [K,N] ldb. All tile dims divide M/N/K exactly.
template<int BM,int BN,int BK,int WM,int WN>
__global__ void __launch_bounds__(((BM/WM)*(BN/WN))*32, 2)
mma_gemm(const float* __restrict__ A, const float* __restrict__ Bm,
         const float* __restrict__ bias, const float* __restrict__ res,
         float* __restrict__ C,
         int M, int N, int K, int lda, int ldb, int ldc,
         long long sAb, long long sAh, long long sBb, long long sBh,
         long long sCb, long long sCh, int Hdim,
         float alpha, int relu)
{
    constexpr int WARPS_M = BM/WM;
    constexpr int WARPS_N = BN/WN;
    constexpr int THREADS = WARPS_M*WARPS_N*32;
    constexpr int MT = WM/16;
    constexpr int NT = WN/8;
    constexpr int PAD = 8;

    int z = blockIdx.z;
    int bb = z / Hdim, hh = z % Hdim;
    A  += bb*sAb + hh*sAh;
    Bm += bb*sBb + hh*sBh;
    C  += bb*sCb + hh*sCh;
    if (res) res += bb*sCb + hh*sCh;

    __shared__ uint32_t As[2][BK][BM+PAD];
    __shared__ uint32_t Bs[2][BK][BN+PAD];

    int tid = threadIdx.x;
    int wid = tid >> 5;
    int lane = tid & 31;
    int grp = lane >> 2;       // 0..7
    int qid = lane & 3;        // 0..3
    int warpRow = wid / WARPS_N;
    int warpCol = wid % WARPS_N;

    int row0 = blockIdx.y * BM;
    int col0 = blockIdx.x * BN;

    // ---- staging mapping ----
    constexpr int A_F4   = BK/4;                  // float4 per A row
    constexpr int A_RPP  = THREADS / A_F4;        // rows per pass
    constexpr int A_LD   = BM / A_RPP;            // passes
    constexpr int B_F4   = BN/4;
    constexpr int B_RPP  = THREADS / B_F4;
    constexpr int B_LD   = BK / B_RPP;

    int aR = tid / A_F4;
    int aC = (tid % A_F4)*4;
    int bR = tid / B_F4;
    int bC = (tid % B_F4)*4;

    float4 aReg[A_LD];
    float4 bReg[B_LD];

    float acc[MT][NT][4];
    #pragma unroll
    for (int i=0;i<MT;i++)
        #pragma unroll
        for (int j=0;j<NT;j++) {
            acc[i][j][0]=0.f; acc[i][j][1]=0.f; acc[i][j][2]=0.f; acc[i][j][3]=0.f;
        }

    // ---- prologue: tile 0 ----
    #pragma unroll
    for (int p=0;p<A_LD;p++)
        aReg[p] = *(const float4*)(A + (long long)(row0 + aR + p*A_RPP)*lda + aC);
    #pragma unroll
    for (int p=0;p<B_LD;p++)
        bReg[p] = *(const float4*)(Bm + (long long)(bR + p*B_RPP)*ldb + col0 + bC);
    #pragma unroll
    for (int p=0;p<A_LD;p++) {
        As[0][aC+0][aR+p*A_RPP] = f2tf32(aReg[p].x);
        As[0][aC+1][aR+p*A_RPP] = f2tf32(aReg[p].y);
        As[0][aC+2][aR+p*A_RPP] = f2tf32(aReg[p].z);
        As[0][aC+3][aR+p*A_RPP] = f2tf32(aReg[p].w);
    }
    #pragma unroll
    for (int p=0;p<B_LD;p++) {
        uint4 u; u.x=f2tf32(bReg[p].x); u.y=f2tf32(bReg[p].y);
        u.z=f2tf32(bReg[p].z); u.w=f2tf32(bReg[p].w);
        *(uint4*)&Bs[0][bR+p*B_RPP][bC] = u;
    }
    __syncthreads();

    int nIter = K / BK;
    for (int it = 0; it < nIter; it++) {
        int cur = it & 1, nxt = cur ^ 1;
        bool hasNext = (it + 1 < nIter);
        int k0n = (it+1)*BK;

        if (hasNext) {
            #pragma unroll
            for (int p=0;p<A_LD;p++)
                aReg[p] = *(const float4*)(A + (long long)(row0 + aR + p*A_RPP)*lda + k0n + aC);
            #pragma unroll
            for (int p=0;p<B_LD;p++)
                bReg[p] = *(const float4*)(Bm + (long long)(k0n + bR + p*B_RPP)*ldb + col0 + bC);
        }

        // ---- compute current tile ----
        #pragma unroll
        for (int ks = 0; ks < BK/8; ks++) {
            int kb = ks*8;
            uint32_t af[MT][4];
            uint32_t bf[NT][2];
            #pragma unroll
            for (int mt=0; mt<MT; mt++) {
                int r = warpRow*WM + mt*16 + grp;
                af[mt][0] = As[cur][kb+qid  ][r];
                af[mt][1] = As[cur][kb+qid  ][r+8];
                af[mt][2] = As[cur][kb+qid+4][r];
                af[mt][3] = As[cur][kb+qid+4][r+8];
            }
            #pragma unroll
            for (int nt=0; nt<NT; nt++) {
                int c = warpCol*WN + nt*8 + grp;
                bf[nt][0] = Bs[cur][kb+qid  ][c];
                bf[nt][1] = Bs[cur][kb+qid+4][c];
            }
            #pragma unroll
            for (int mt=0; mt<MT; mt++)
                #pragma unroll
                for (int nt=0; nt<NT; nt++)
                    mma_tf32(acc[mt][nt], af[mt], bf[nt]);
        }

        if (hasNext) {
            #pragma unroll
            for (int p=0;p<A_LD;p++) {
                As[nxt][aC+0][aR+p*A_RPP] = f2tf32(aReg[p].x);
                As[nxt][aC+1][aR+p*A_RPP] = f2tf32(aReg[p].y);
                As[nxt][aC+2][aR+p*A_RPP] = f2tf32(aReg[p].z);
                As[nxt][aC+3][aR+p*A_RPP] = f2tf32(aReg[p].w);
            }
            #pragma unroll
            for (int p=0;p<B_LD;p++) {
                uint4 u; u.x=f2tf32(bReg[p].x); u.y=f2tf32(bReg[p].y);
                u.z=f2tf32(bReg[p].z); u.w=f2tf32(bReg[p].w);
                *(uint4*)&Bs[nxt][bR+p*B_RPP][bC] = u;
            }
        }
        __syncthreads();
    }

    // ---- epilogue ----
    #pragma unroll
    for (int mt=0; mt<MT; mt++) {
        int rA = row0 + warpRow*WM + mt*16 + grp;
        int rB = rA + 8;
        #pragma unroll
        for (int nt=0; nt<NT; nt++) {
            int c = col0 + warpCol*WN + nt*8 + qid*2;
            float v0 = acc[mt][nt][0]*alpha;
            float v1 = acc[mt][nt][1]*alpha;
            float v2 = acc[mt][nt][2]*alpha;
            float v3 = acc[mt][nt][3]*alpha;
            if (bias) {
                float2 bb2 = *(const float2*)(bias + c);
                v0 += bb2.x; v1 += bb2.y; v2 += bb2.x; v3 += bb2.y;
            }
            if (relu) {
                v0 = fmaxf(v0,0.f); v1 = fmaxf(v1,0.f);
                v2 = fmaxf(v2,0.f); v3 = fmaxf(v3,0.f);
            }
            if (res) {
                float2 rA2 = *(const float2*)(res + (long long)rA*ldc + c);
                float2 rB2 = *(const float2*)(res + (long long)rB*ldc + c);
                v0 += rA2.x; v1 += rA2.y; v2 += rB2.x; v3 += rB2.y;
            }
            *(float2*)(C + (long long)rA*ldc + c) = make_float2(v0, v1);
            *(float2*)(C + (long long)rB*ldc + c) = make_float2(v2, v3);
        }
    }
}

// ---------------- attention scores: S[bh, t, s] = scale * q_t . k_s (causal) ----------------
__global__ void __launch_bounds__(256)
scores_kernel(const float* __restrict__ q, const float* __restrict__ k,
              float* __restrict__ scores)
{
    int si = blockIdx.x, ti = blockIdx.y, bh = blockIdx.z;
    if (si > ti) return;                    // fully masked tile, never read later
    int b = bh / NHEAD, h = bh % NHEAD;
    const float* Q  = q + (long long)b*SEQ*NEMBD + h*HSZ;
    const float* Kp = k + (long long)b*SEQ*NEMBD + h*HSZ;

    __shared__ float Qs[HSZ][65];
    __shared__ float Ks[HSZ][65];

    int tid = threadIdx.x;
    for (int i = tid; i < 64*16; i += 256) {
        int r = i >> 4, c4 = (i & 15) << 2;
        float4 vq = *(const float4*)(Q  + (long long)(ti*64 + r)*NEMBD + c4);
        Qs[c4+0][r]=vq.x; Qs[c4+1][r]=vq.y; Qs[c4+2][r]=vq.z; Qs[c4+3][r]=vq.w;
        float4 vk = *(const float4*)(Kp + (long long)(si*64 + r)*NEMBD + c4);
        Ks[c4+0][r]=vk.x; Ks[c4+1][r]=vk.y; Ks[c4+2][r]=vk.z; Ks[c4+3][r]=vk.w;
    }
    __syncthreads();

    int ty = tid / 16, tx = tid % 16;
    float acc[4][4];
    #pragma unroll
    for (int i=0;i<4;i++) { acc[i][0]=0.f; acc[i][1]=0.f; acc[i][2]=0.f; acc[i][3]=0.f; }

    #pragma unroll
    for (int kk = 0; kk < HSZ; kk++) {
        float ra[4], rb[4];
        #pragma unroll
        for (int i=0;i<4;i++) ra[i] = Qs[kk][ty*4+i];
        #pragma unroll
        for (int j=0;j<4;j++) rb[j] = Ks[kk][tx*4+j];
        #pragma unroll
        for (int i=0;i<4;i++)
            #pragma unroll
            for (int j=0;j<4;j++) acc[i][j] = fmaf(ra[i], rb[j], acc[i][j]);
    }

    const float scale = 0.03125f;          // 1024^-0.5
    float* S = scores + (long long)bh*SEQ*SEQ;
    #pragma unroll
    for (int i=0;i<4;i++) {
        int tt = ti*64 + ty*4 + i;
        #pragma unroll
        for (int j=0;j<4;j++) {
            int ss = si*64 + tx*4 + j;
            S[(long long)tt*SEQ + ss] = (ss <= tt) ? acc[i][j]*scale : -INFINITY;
        }
    }
}

// ---------------- causal softmax, in-place; zeros above diagonal ----------------
__global__ void __launch_bounds__(256)
softmax_kernel(float* __restrict__ scores)
{
    long long row = blockIdx.x;                 // B*H*SEQ rows
    int t   = (int)(row % SEQ);
    int len = t + 1;
    float* p = scores + row * (long long)SEQ;
    int tid = threadIdx.x;

    float m = -INFINITY;
    for (int i = tid; i < len; i += 256) m = fmaxf(m, p[i]);
    #pragma unroll
    for (int o=16;o>0;o>>=1) m = fmaxf(m, __shfl_xor_sync(0xffffffffu, m, o));
    __shared__ float sm[8];
    int wid = tid >> 5, lid = tid & 31;
    if (lid == 0) sm[wid] = m;
    __syncthreads();
    if (wid == 0) {
        float a = (lid < 8) ? sm[lid] : -INFINITY;
        #pragma unroll
        for (int o=4;o>0;o>>=1) a = fmaxf(a, __shfl_xor_sync(0xffffffffu, a, o));
        if (lid == 0) sm[0] = a;
    }
    __syncthreads();
    m = sm[0];

    float s = 0.f;
    for (int i = tid; i < len; i += 256) s += __expf(p[i] - m);
    #pragma unroll
    for (int o=16;o>0;o>>=1) s += __shfl_xor_sync(0xffffffffu, s, o);
    __shared__ float ssum[8];
    if (lid == 0) ssum[wid] = s;
    __syncthreads();
    if (wid == 0) {
        float a = (lid < 8) ? ssum[lid] : 0.f;
        #pragma unroll
        for (int o=4;o>0;o>>=1) a += __shfl_xor_sync(0xffffffffu, a, o);
        if (lid == 0) ssum[0] = a;
    }
    __syncthreads();
    float inv = 1.0f / ssum[0];

    for (int i = tid; i < SEQ; i += 256)
        p[i] = (i < len) ? __expf(p[i] - m) * inv : 0.f;
}

// ---------------- launch ----------------
extern "C" void kernel_launch(void* const* d_in, const int* in_sizes, int n_in,
                              void* d_out, int out_size)
{
    const float* x     = (const float*)d_in[0];
    const float* Wq    = (const float*)d_in[1];
    const float* Wk    = (const float*)d_in[2];
    const float* Wv    = (const float*)d_in[3];
    const float* Wproj = (const float*)d_in[4];
    const float* bproj = (const float*)d_in[5];
    const float* W1    = (const float*)d_in[6];
    const float* b1    = (const float*)d_in[7];
    const float* W2    = (const float*)d_in[8];
    const float* b2    = (const float*)d_in[9];
    const float* ln1w  = (const float*)d_in[10];
    const float* ln1b  = (const float*)d_in[11];
    const float* ln2w  = (const float*)d_in[12];
    const float* ln2b  = (const float*)d_in[13];
    float* out = (float*)d_out;

    float *ph, *pq, *pk, *pv, *pattn, *px2, *pf1, *pscores;
    cudaGetSymbolAddress((void**)&ph,     g_h);
    cudaGetSymbolAddress((void**)&pq,     g_q);
    cudaGetSymbolAddress((void**)&pk,     g_k);
    cudaGetSymbolAddress((void**)&pv,     g_v);
    cudaGetSymbolAddress((void**)&pattn,  g_attn);
    cudaGetSymbolAddress((void**)&px2,    g_x2);
    cudaGetSymbolAddress((void**)&pf1,    g_f1);
    cudaGetSymbolAddress((void**)&pscores,g_scores);

    const long long Z = 0;

    // 1) LN1
    ln_kernel<<<BT, 256>>>(x, ln1w, ln1b, ph);

    // 2) Q,K,V projections  (M=4096,N=1024,K=1024) -- tf32 tensor cores
    {
        dim3 grid(NEMBD/128, BT/128, 1);
        mma_gemm<128,128,16,64,32><<<grid, 256>>>(ph, Wq, nullptr, nullptr, pq,
            BT, NEMBD, NEMBD, NEMBD, NEMBD, NEMBD, Z,Z,Z,Z,Z,Z, 1, 1.0f, 0);
        mma_gemm<128,128,16,64,32><<<grid, 256>>>(ph, Wk, nullptr, nullptr, pk,
            BT, NEMBD, NEMBD, NEMBD, NEMBD, NEMBD, Z,Z,Z,Z,Z,Z, 1, 1.0f, 0);
        mma_gemm<128,128,16,64,32><<<grid, 256>>>(ph, Wv, nullptr, nullptr, pv,
            BT, NEMBD, NEMBD, NEMBD, NEMBD, NEMBD, Z,Z,Z,Z,Z,Z, 1, 1.0f, 0);
    }

    // 3) causal scores
    {
        dim3 grid(SEQ/64, SEQ/64, BATCH*NHEAD);
        scores_kernel<<<grid, 256>>>(pq, pk, pscores);
    }

    // 4) softmax (writes zeros above diagonal)
    softmax_kernel<<<BATCH*NHEAD*SEQ, 256>>>(pscores);

    // 5) attn = P @ V   (per (b,h): M=2048,N=64,K=2048) -- tf32 tensor cores
    {
        dim3 grid(1, SEQ/128, BATCH*NHEAD);
        mma_gemm<128,64,16,32,32><<<grid, 256>>>(pscores, pv, nullptr, nullptr, pattn,
            SEQ, HSZ, SEQ, SEQ, NEMBD, NEMBD,
            (long long)NHEAD*SEQ*SEQ, (long long)SEQ*SEQ,
            (long long)SEQ*NEMBD, (long long)HSZ,
            (long long)SEQ*NEMBD, (long long)HSZ,
            NHEAD, 1.0f, 0);
    }

    // 6) x2 = x + attn @ Wproj + bproj
    {
        dim3 grid(NEMBD/128, BT/128, 1);
        mma_gemm<128,128,16,64,32><<<grid, 256>>>(pattn, Wproj, bproj, x, px2,
            BT, NEMBD, NEMBD, NEMBD, NEMBD, NEMBD, Z,Z,Z,Z,Z,Z, 1, 1.0f, 0);
    }

    // 7) LN2
    ln_kernel<<<BT, 256>>>(px2, ln2w, ln2b, ph);

    // 8) f1 = relu(h2 @ W1 + b1)   (M=4096,N=4096,K=1024)
    {
        dim3 grid(FFDIM/128, BT/128, 1);
        mma_gemm<128,128,16,64,32><<<grid, 256>>>(ph, W1, b1, nullptr, pf1,
            BT, FFDIM, NEMBD, NEMBD, FFDIM, FFDIM, Z,Z,Z,Z,Z,Z, 1, 1.0f, 1);
    }

    // 9) out = x2 + f1 @ W2 + b2   (M=4096,N=1024,K=4096)
    {
        dim3 grid(NEMBD/128, BT/128, 1);
        mma_gemm<128,128,16,64,32><<<grid, 256>>>(pf1, W2, b2, px2, out,
            BT, NEMBD, FFDIM, FFDIM, NEMBD, NEMBD, Z,Z,Z,Z,Z,Z, 1, 1.0f, 0);
    }
}

// round 7
// speedup vs baseline: 2.2364x; 1.0734x over previous
#include <cuda_runtime.h>
#include <cuda_bf16.h>
#include <math.h>
#include <stdint.h>

#define BATCH 2
#define SEQ   2048
#define NEMBD 1024
#define NHEAD 16
#define HSZ   64
#define FFDIM 4096
#define BT    (BATCH*SEQ)      // 4096 rows
#define LN_EPS 1e-5f

// ---------------- scratch (device globals; no allocation allowed) ----------------
__device__ float g_h[(size_t)BT*NEMBD];
__device__ float g_q[(size_t)BT*NEMBD];
__device__ float g_k[(size_t)BT*NEMBD];
__device__ float g_v[(size_t)BT*NEMBD];
__device__ float g_attn[(size_t)BT*NEMBD];
__device__ float g_x2[(size_t)BT*NEMBD];
__device__ float g_f1[(size_t)BT*FFDIM];
__device__ float g_scores[(size_t)BATCH*NHEAD*SEQ*SEQ];   // 512 MB

// ---------------- helpers ----------------
__device__ __forceinline__ uint32_t f2tf32(float x) {
    uint32_t r;
    asm("cvt.rna.tf32.f32 %0, %1;" : "=r"(r) : "f"(x));
    return r;
}

__device__ __forceinline__ void mma_tf32(float* c, const uint32_t* a, const uint32_t* b) {
    asm volatile(
        "mma.sync.aligned.m16n8k8.row.col.f32.tf32.tf32.f32 "
        "{%0,%1,%2,%3}, {%4,%5,%6,%7}, {%8,%9}, {%0,%1,%2,%3};"
        : "+f"(c[0]), "+f"(c[1]), "+f"(c[2]), "+f"(c[3])
        : "r"(a[0]), "r"(a[1]), "r"(a[2]), "r"(a[3]), "r"(b[0]), "r"(b[1]));
}

__device__ __forceinline__ void cp_async16(uint32_t saddr, const void* gaddr) {
    asm volatile("cp.async.cg.shared.global [%0], [%1], 16;" :: "r"(saddr), "l"(gaddr));
}
__device__ __forceinline__ void cp_commit() {
    asm volatile("cp.async.commit_group;");
}
template<int N>
__device__ __forceinline__ void cp_wait() {
    asm volatile("cp.async.wait_group %0;" :: "n"(N));
}
__device__ __forceinline__ uint32_t smem_u32(const void* p) {
    return (uint32_t)__cvta_generic_to_shared(p);
}

// ---------------- LayerNorm: one block per row, 256 threads, C=1024 ----------------
__global__ void ln_kernel(const float* __restrict__ x, const float* __restrict__ w,
                          const float* __restrict__ b, float* __restrict__ out)
{
    int row = blockIdx.x;
    const float4* xr = (const float4*)(x + (size_t)row*NEMBD);
    int t = threadIdx.x;
    float4 v = xr[t];
    float s  = v.x + v.y + v.z + v.w;
    float s2 = v.x*v.x + v.y*v.y + v.z*v.z + v.w*v.w;
    #pragma unroll
    for (int o = 16; o > 0; o >>= 1) {
        s  += __shfl_xor_sync(0xffffffffu, s,  o);
        s2 += __shfl_xor_sync(0xffffffffu, s2, o);
    }
    __shared__ float ss[8], ss2[8];
    int wid = t >> 5, lid = t & 31;
    if (lid == 0) { ss[wid] = s; ss2[wid] = s2; }
    __syncthreads();
    if (wid == 0) {
        float a  = (lid < 8) ? ss[lid]  : 0.f;
        float a2 = (lid < 8) ? ss2[lid] : 0.f;
        #pragma unroll
        for (int o = 4; o > 0; o >>= 1) {
            a  += __shfl_xor_sync(0xffffffffu, a,  o);
            a2 += __shfl_xor_sync(0xffffffffu, a2, o);
        }
        if (lid == 0) { ss[0] = a; ss2[0] = a2; }
    }
    __syncthreads();
    float mu  = ss[0]  * (1.0f/NEMBD);
    float var = ss2[0] * (1.0f/NEMBD) - mu*mu;
    float inv = rsqrtf(var + LN_EPS);
    const float4 wv = ((const float4*)w)[t];
    const float4 bv = ((const float4*)b)[t];
    float4 o4;
    o4.x = (v.x - mu)*inv*wv.x + bv.x;
    o4.y = (v.y - mu)*inv*wv.y + bv.y;
    o4.z = (v.z - mu)*inv*wv.z + bv.z;
    o4.w = (v.w - mu)*inv*wv.w + bv.w;
    ((float4*)(out + (size_t)row*NEMBD))[t] = o4;
}

// ---------------- tf32 tensor-core GEMM with cp.async pipeline ----------------
// C[m,n] = alpha * sum_k A[m,k]*B[k,n]  (+bias[n]) (relu) (+res[m,n]); batched via z.
// A row-major [M,K] lda, B row-major [K,N] ldb. All tile dims divide M/N/K exactly.
template<int BM,int BN,int BK,int WM,int WN,int STAGES>
__global__ void __launch_bounds__(((BM/WM)*(BN/WN))*32, 2)
mma_gemm(const float* __restrict__ A, const float* __restrict__ Bm,
         const float* __restrict__ bias, const float* __restrict__ res,
         float* __restrict__ C,
         int M, int N, int K, int lda, int ldb, int ldc,
         long long sAb, long long sAh, long long sBb, long long sBh,
         long long sCb, long long sCh, int Hdim,
         float alpha, int relu)
{
    constexpr int WARPS_M = BM/WM;
    constexpr int WARPS_N = BN/WN;
    constexpr int THREADS = WARPS_M*WARPS_N*32;
    constexpr int MT = WM/16;
    constexpr int NT = WN/8;
    constexpr int A_STRIDE = BK + 4;      // words; stride 20 -> conflict-free frag loads
    constexpr int B_STRIDE = BN + 8;      // words; stride%32==8 -> conflict-free

    constexpr int A_CHUNKS = BM*(BK/4);   // 16B chunks per A tile
    constexpr int B_CHUNKS = BK*(BN/4);
    constexpr int A_ITERS  = A_CHUNKS / THREADS;
    constexpr int B_ITERS  = (B_CHUNKS + THREADS - 1) / THREADS;

    extern __shared__ float smem[];
    float* Asf = smem;                               // [STAGES][BM][A_STRIDE]
    float* Bsf = smem + (size_t)STAGES*BM*A_STRIDE;  // [STAGES][BK][B_STRIDE]

    int z = blockIdx.z;
    int bb = z / Hdim, hh = z % Hdim;
    A  += bb*sAb + hh*sAh;
    Bm += bb*sBb + hh*sBh;
    C  += bb*sCb + hh*sCh;
    if (res) res += bb*sCb + hh*sCh;

    int tid = threadIdx.x;
    int wid = tid >> 5;
    int lane = tid & 31;
    int grp = lane >> 2;       // 0..7
    int qid = lane & 3;        // 0..3
    int warpRow = wid / WARPS_N;
    int warpCol = wid % WARPS_N;

    int row0 = blockIdx.y * BM;
    int col0 = blockIdx.x * BN;

    uint32_t sA = smem_u32(Asf);
    uint32_t sB = smem_u32(Bsf);

    float acc[MT][NT][4];
    #pragma unroll
    for (int i=0;i<MT;i++)
        #pragma unroll
        for (int j=0;j<NT;j++) {
            acc[i][j][0]=0.f; acc[i][j][1]=0.f; acc[i][j][2]=0.f; acc[i][j][3]=0.f;
        }

    int nIter = K / BK;

    // ---- async stage issue ----
    auto issue = [&](int s, int buf) {
        #pragma unroll
        for (int t=0; t<A_ITERS; t++) {
            int ch = tid + t*THREADS;
            int r = ch / (BK/4);
            int c = (ch % (BK/4)) * 4;
            cp_async16(sA + (((buf*BM + r)*A_STRIDE + c) << 2),
                       A + (long long)(row0 + r)*lda + s*BK + c);
        }
        #pragma unroll
        for (int t=0; t<B_ITERS; t++) {
            int ch = tid + t*THREADS;
            if (B_CHUNKS % THREADS == 0 || ch < B_CHUNKS) {
                int r = ch / (BN/4);
                int c = (ch % (BN/4)) * 4;
                cp_async16(sB + (((buf*BK + r)*B_STRIDE + c) << 2),
                           Bm + (long long)(s*BK + r)*ldb + col0 + c);
            }
        }
    };

    // prologue: fill STAGES-1 stages
    #pragma unroll
    for (int s=0; s<STAGES-1; s++) {
        if (s < nIter) issue(s, s);
        cp_commit();
    }

    for (int it = 0; it < nIter; it++) {
        cp_wait<STAGES-2>();
        __syncthreads();

        int cur = it % STAGES;
        int nx = it + STAGES - 1;
        if (nx < nIter) issue(nx, nx % STAGES);
        cp_commit();

        const float* Acur = Asf + (size_t)cur*BM*A_STRIDE;
        const float* Bcur = Bsf + (size_t)cur*BK*B_STRIDE;

        #pragma unroll
        for (int ks = 0; ks < BK/8; ks++) {
            int kb = ks*8;
            uint32_t af[MT][4];
            uint32_t bf[NT][2];
            #pragma unroll
            for (int mt=0; mt<MT; mt++) {
                int r = warpRow*WM + mt*16 + grp;
                af[mt][0] = f2tf32(Acur[(r  )*A_STRIDE + kb + qid    ]);
                af[mt][1] = f2tf32(Acur[(r+8)*A_STRIDE + kb + qid    ]);
                af[mt][2] = f2tf32(Acur[(r  )*A_STRIDE + kb + qid + 4]);
                af[mt][3] = f2tf32(Acur[(r+8)*A_STRIDE + kb + qid + 4]);
            }
            #pragma unroll
            for (int nt=0; nt<NT; nt++) {
                int c = warpCol*WN + nt*8 + grp;
                bf[nt][0] = f2tf32(Bcur[(kb + qid    )*B_STRIDE + c]);
                bf[nt][1] = f2tf32(Bcur[(kb + qid + 4)*B_STRIDE + c]);
            }
            #pragma unroll
            for (int mt=0; mt<MT; mt++)
                #pragma unroll
                for (int nt=0; nt<NT; nt++)
                    mma_tf32(acc[mt][nt], af[mt], bf[nt]);
        }
        __syncthreads();
    }

    // ---- epilogue ----
    #pragma unroll
    for (int mt=0; mt<MT; mt++) {
        int rA = row0 + warpRow*WM + mt*16 + grp;
        int rB = rA + 8;
        #pragma unroll
        for (int nt=0; nt<NT; nt++) {
            int c = col0 + warpCol*WN + nt*8 + qid*2;
            float v0 = acc[mt][nt][0]*alpha;
            float v1 = acc[mt][nt][1]*alpha;
            float v2 = acc[mt][nt][2]*alpha;
            float v3 = acc[mt][nt][3]*alpha;
            if (bias) {
                float2 bb2 = *(const float2*)(bias + c);
                v0 += bb2.x; v1 += bb2.y; v2 += bb2.x; v3 += bb2.y;
            }
            if (relu) {
                v0 = fmaxf(v0,0.f); v1 = fmaxf(v1,0.f);
                v2 = fmaxf(v2,0.f); v3 = fmaxf(v3,0.f);
            }
            if (res) {
                float2 rA2 = *(const float2*)(res + (long long)rA*ldc + c);
                float2 rB2 = *(const float2*)(res + (long long)rB*ldc + c);
                v0 += rA2.x; v1 += rA2.y; v2 += rB2.x; v3 += rB2.y;
            }
            *(float2*)(C + (long long)rA*ldc + c) = make_float2(v0, v1);
            *(float2*)(C + (long long)rB*ldc + c) = make_float2(v2, v3);
        }
    }
}

// ---------------- attention scores: S[bh, t, s] = scale * q_t . k_s (causal) ----------------
__global__ void __launch_bounds__(256)
scores_kernel(const float* __restrict__ q, const float* __restrict__ k,
              float* __restrict__ scores)
{
    int si = blockIdx.x, ti = blockIdx.y, bh = blockIdx.z;
    if (si > ti) return;                    // fully masked tile, never read later
    int b = bh / NHEAD, h = bh % NHEAD;
    const float* Q  = q + (long long)b*SEQ*NEMBD + h*HSZ;
    const float* Kp = k + (long long)b*SEQ*NEMBD + h*HSZ;

    __shared__ float Qs[HSZ][65];
    __shared__ float Ks[HSZ][65];

    int tid = threadIdx.x;
    for (int i = tid; i < 64*16; i += 256) {
        int r = i >> 4, c4 = (i & 15) << 2;
        float4 vq = *(const float4*)(Q  + (long long)(ti*64 + r)*NEMBD + c4);
        Qs[c4+0][r]=vq.x; Qs[c4+1][r]=vq.y; Qs[c4+2][r]=vq.z; Qs[c4+3][r]=vq.w;
        float4 vk = *(const float4*)(Kp + (long long)(si*64 + r)*NEMBD + c4);
        Ks[c4+0][r]=vk.x; Ks[c4+1][r]=vk.y; Ks[c4+2][r]=vk.z; Ks[c4+3][r]=vk.w;
    }
    __syncthreads();

    int ty = tid / 16, tx = tid % 16;
    float acc[4][4];
    #pragma unroll
    for (int i=0;i<4;i++) { acc[i][0]=0.f; acc[i][1]=0.f; acc[i][2]=0.f; acc[i][3]=0.f; }

    #pragma unroll
    for (int kk = 0; kk < HSZ; kk++) {
        float ra[4], rb[4];
        #pragma unroll
        for (int i=0;i<4;i++) ra[i] = Qs[kk][ty*4+i];
        #pragma unroll
        for (int j=0;j<4;j++) rb[j] = Ks[kk][tx*4+j];
        #pragma unroll
        for (int i=0;i<4;i++)
            #pragma unroll
            for (int j=0;j<4;j++) acc[i][j] = fmaf(ra[i], rb[j], acc[i][j]);
    }

    const float scale = 0.03125f;          // 1024^-0.5
    float* S = scores + (long long)bh*SEQ*SEQ;
    #pragma unroll
    for (int i=0;i<4;i++) {
        int tt = ti*64 + ty*4 + i;
        #pragma unroll
        for (int j=0;j<4;j++) {
            int ss = si*64 + tx*4 + j;
            S[(long long)tt*SEQ + ss] = (ss <= tt) ? acc[i][j]*scale : -INFINITY;
        }
    }
}

// ---------------- causal softmax, in-place; zeros above diagonal ----------------
__global__ void __launch_bounds__(256)
softmax_kernel(float* __restrict__ scores)
{
    long long row = blockIdx.x;                 // B*H*SEQ rows
    int t   = (int)(row % SEQ);
    int len = t + 1;
    float* p = scores + row * (long long)SEQ;
    int tid = threadIdx.x;

    float m = -INFINITY;
    for (int i = tid; i < len; i += 256) m = fmaxf(m, p[i]);
    #pragma unroll
    for (int o=16;o>0;o>>=1) m = fmaxf(m, __shfl_xor_sync(0xffffffffu, m, o));
    __shared__ float sm[8];
    int wid = tid >> 5, lid = tid & 31;
    if (lid == 0) sm[wid] = m;
    __syncthreads();
    if (wid == 0) {
        float a = (lid < 8) ? sm[lid] : -INFINITY;
        #pragma unroll
        for (int o=4;o>0;o>>=1) a = fmaxf(a, __shfl_xor_sync(0xffffffffu, a, o));
        if (lid == 0) sm[0] = a;
    }
    __syncthreads();
    m = sm[0];

    float s = 0.f;
    for (int i = tid; i < len; i += 256) s += __expf(p[i] - m);
    #pragma unroll
    for (int o=16;o>0;o>>=1) s += __shfl_xor_sync(0xffffffffu, s, o);
    __shared__ float ssum[8];
    if (lid == 0) ssum[wid] = s;
    __syncthreads();
    if (wid == 0) {
        float a = (lid < 8) ? ssum[lid] : 0.f;
        #pragma unroll
        for (int o=4;o>0;o>>=1) a += __shfl_xor_sync(0xffffffffu, a, o);
        if (lid == 0) ssum[0] = a;
    }
    __syncthreads();
    float inv = 1.0f / ssum[0];

    for (int i = tid; i < SEQ; i += 256)
        p[i] = (i < len) ? __expf(p[i] - m) * inv : 0.f;
}

// ---------------- launch ----------------
extern "C" void kernel_launch(void* const* d_in, const int* in_sizes, int n_in,
                              void* d_out, int out_size)
{
    const float* x     = (const float*)d_in[0];
    const float* Wq    = (const float*)d_in[1];
    const float* Wk    = (const float*)d_in[2];
    const float* Wv    = (const float*)d_in[3];
    const float* Wproj = (const float*)d_in[4];
    const float* bproj = (const float*)d_in[5];
    const float* W1    = (const float*)d_in[6];
    const float* b1    = (const float*)d_in[7];
    const float* W2    = (const float*)d_in[8];
    const float* b2    = (const float*)d_in[9];
    const float* ln1w  = (const float*)d_in[10];
    const float* ln1b  = (const float*)d_in[11];
    const float* ln2w  = (const float*)d_in[12];
    const float* ln2b  = (const float*)d_in[13];
    float* out = (float*)d_out;

    float *ph, *pq, *pk, *pv, *pattn, *px2, *pf1, *pscores;
    cudaGetSymbolAddress((void**)&ph,     g_h);
    cudaGetSymbolAddress((void**)&pq,     g_q);
    cudaGetSymbolAddress((void**)&pk,     g_k);
    cudaGetSymbolAddress((void**)&pv,     g_v);
    cudaGetSymbolAddress((void**)&pattn,  g_attn);
    cudaGetSymbolAddress((void**)&px2,    g_x2);
    cudaGetSymbolAddress((void**)&pf1,    g_f1);
    cudaGetSymbolAddress((void**)&pscores,g_scores);

    const long long Z = 0;

    // dynamic smem sizes
    constexpr int ST = 4;
    constexpr size_t SMEM_G128 = (size_t)(ST*128*(16+4) + ST*16*(128+8)) * 4;  // 75776
    constexpr size_t SMEM_G64  = (size_t)(ST*128*(16+4) + ST*16*(64+8))  * 4;  // 59392

    auto* kern128 = mma_gemm<128,128,16,64,32,ST>;
    auto* kern64  = mma_gemm<128,64,16,32,32,ST>;
    cudaFuncSetAttribute(kern128, cudaFuncAttributeMaxDynamicSharedMemorySize, (int)SMEM_G128);
    cudaFuncSetAttribute(kern64,  cudaFuncAttributeMaxDynamicSharedMemorySize, (int)SMEM_G64);

    // 1) LN1
    ln_kernel<<<BT, 256>>>(x, ln1w, ln1b, ph);

    // 2) Q,K,V projections  (M=4096,N=1024,K=1024)
    {
        dim3 grid(NEMBD/128, BT/128, 1);
        kern128<<<grid, 256, SMEM_G128>>>(ph, Wq, nullptr, nullptr, pq,
            BT, NEMBD, NEMBD, NEMBD, NEMBD, NEMBD, Z,Z,Z,Z,Z,Z, 1, 1.0f, 0);
        kern128<<<grid, 256, SMEM_G128>>>(ph, Wk, nullptr, nullptr, pk,
            BT, NEMBD, NEMBD, NEMBD, NEMBD, NEMBD, Z,Z,Z,Z,Z,Z, 1, 1.0f, 0);
        kern128<<<grid, 256, SMEM_G128>>>(ph, Wv, nullptr, nullptr, pv,
            BT, NEMBD, NEMBD, NEMBD, NEMBD, NEMBD, Z,Z,Z,Z,Z,Z, 1, 1.0f, 0);
    }

    // 3) causal scores
    {
        dim3 grid(SEQ/64, SEQ/64, BATCH*NHEAD);
        scores_kernel<<<grid, 256>>>(pq, pk, pscores);
    }

    // 4) softmax (writes zeros above diagonal)
    softmax_kernel<<<BATCH*NHEAD*SEQ, 256>>>(pscores);

    // 5) attn = P @ V   (per (b,h): M=2048,N=64,K=2048)
    {
        dim3 grid(1, SEQ/128, BATCH*NHEAD);
        kern64<<<grid, 256, SMEM_G64>>>(pscores, pv, nullptr, nullptr, pattn,
            SEQ, HSZ, SEQ, SEQ, NEMBD, NEMBD,
            (long long)NHEAD*SEQ*SEQ, (long long)SEQ*SEQ,
            (long long)SEQ*NEMBD, (long long)HSZ,
            (long long)SEQ*NEMBD, (long long)HSZ,
            NHEAD, 1.0f, 0);
    }

    // 6) x2 = x + attn @ Wproj + bproj
    {
        dim3 grid(NEMBD/128, BT/128, 1);
        kern128<<<grid, 256, SMEM_G128>>>(pattn, Wproj, bproj, x, px2,
            BT, NEMBD, NEMBD, NEMBD, NEMBD, NEMBD, Z,Z,Z,Z,Z,Z, 1, 1.0f, 0);
    }

    // 7) LN2
    ln_kernel<<<BT, 256>>>(px2, ln2w, ln2b, ph);

    // 8) f1 = relu(h2 @ W1 + b1)   (M=4096,N=4096,K=1024)
    {
        dim3 grid(FFDIM/128, BT/128, 1);
        kern128<<<grid, 256, SMEM_G128>>>(ph, W1, b1, nullptr, pf1,
            BT, FFDIM, NEMBD, NEMBD, FFDIM, FFDIM, Z,Z,Z,Z,Z,Z, 1, 1.0f, 1);
    }

    // 9) out = x2 + f1 @ W2 + b2   (M=4096,N=1024,K=4096)
    {
        dim3 grid(NEMBD/128, BT/128, 1);
        kern128<<<grid, 256, SMEM_G128>>>(pf1, W2, b2, px2, out,
            BT, NEMBD, FFDIM, FFDIM, NEMBD, NEMBD, Z,Z,Z,Z,Z,Z, 1, 1.0f, 0);
    }
}

// round 8
// speedup vs baseline: 3.1311x; 1.4000x over previous
#include <cuda_runtime.h>
#include <cuda_bf16.h>
#include <math.h>
#include <stdint.h>

#define BATCH 2
#define SEQ   2048
#define NEMBD 1024
#define NHEAD 16
#define HSZ   64
#define FFDIM 4096
#define BT    (BATCH*SEQ)      // 4096 rows
#define LN_EPS 1e-5f
#define ATT_SCALE 0.03125f     // 1024^-0.5

// ---------------- scratch (device globals; no allocation allowed) ----------------
__device__ float g_h[(size_t)BT*NEMBD];
__device__ float g_q[(size_t)BT*NEMBD];
__device__ float g_k[(size_t)BT*NEMBD];
__device__ float g_v[(size_t)BT*NEMBD];
__device__ float g_attn[(size_t)BT*NEMBD];
__device__ float g_x2[(size_t)BT*NEMBD];
__device__ float g_f1[(size_t)BT*FFDIM];
__device__ float g_wr[(size_t)12*1024*1024];   // rounded weights: Wq,Wk,Wv,Wproj(1M ea) W1,W2(4M ea)

// ---------------- helpers ----------------
__device__ __forceinline__ uint32_t f2tf32(float x) {
    uint32_t r;
    asm("cvt.rna.tf32.f32 %0, %1;" : "=r"(r) : "f"(x));
    return r;
}
__device__ __forceinline__ float rndtf(float x) { return __uint_as_float(f2tf32(x)); }

__device__ __forceinline__ void mma_tf32(float* c, const uint32_t* a, const uint32_t* b) {
    asm volatile(
        "mma.sync.aligned.m16n8k8.row.col.f32.tf32.tf32.f32 "
        "{%0,%1,%2,%3}, {%4,%5,%6,%7}, {%8,%9}, {%0,%1,%2,%3};"
        : "+f"(c[0]), "+f"(c[1]), "+f"(c[2]), "+f"(c[3])
        : "r"(a[0]), "r"(a[1]), "r"(a[2]), "r"(a[3]), "r"(b[0]), "r"(b[1]));
}

__device__ __forceinline__ void cp_async16(uint32_t saddr, const void* gaddr) {
    asm volatile("cp.async.cg.shared.global [%0], [%1], 16;" :: "r"(saddr), "l"(gaddr));
}
__device__ __forceinline__ void cp_commit() {
    asm volatile("cp.async.commit_group;");
}
template<int N>
__device__ __forceinline__ void cp_wait() {
    asm volatile("cp.async.wait_group %0;" :: "n"(N));
}
__device__ __forceinline__ uint32_t smem_u32(const void* p) {
    return (uint32_t)__cvta_generic_to_shared(p);
}

// ---------------- weight pre-rounding (fp32 -> tf32-rounded fp32) ----------------
__global__ void round_w_kernel(const float* __restrict__ in, float* __restrict__ out, int n4)
{
    int i = blockIdx.x*blockDim.x + threadIdx.x;
    if (i < n4) {
        float4 v = ((const float4*)in)[i];
        v.x = rndtf(v.x); v.y = rndtf(v.y); v.z = rndtf(v.z); v.w = rndtf(v.w);
        ((float4*)out)[i] = v;
    }
}

// ---------------- LayerNorm: one block per row; output rounded to tf32 ----------------
__global__ void ln_kernel(const float* __restrict__ x, const float* __restrict__ w,
                          const float* __restrict__ b, float* __restrict__ out)
{
    int row = blockIdx.x;
    const float4* xr = (const float4*)(x + (size_t)row*NEMBD);
    int t = threadIdx.x;
    float4 v = xr[t];
    float s  = v.x + v.y + v.z + v.w;
    float s2 = v.x*v.x + v.y*v.y + v.z*v.z + v.w*v.w;
    #pragma unroll
    for (int o = 16; o > 0; o >>= 1) {
        s  += __shfl_xor_sync(0xffffffffu, s,  o);
        s2 += __shfl_xor_sync(0xffffffffu, s2, o);
    }
    __shared__ float ss[8], ss2[8];
    int wid = t >> 5, lid = t & 31;
    if (lid == 0) { ss[wid] = s; ss2[wid] = s2; }
    __syncthreads();
    if (wid == 0) {
        float a  = (lid < 8) ? ss[lid]  : 0.f;
        float a2 = (lid < 8) ? ss2[lid] : 0.f;
        #pragma unroll
        for (int o = 4; o > 0; o >>= 1) {
            a  += __shfl_xor_sync(0xffffffffu, a,  o);
            a2 += __shfl_xor_sync(0xffffffffu, a2, o);
        }
        if (lid == 0) { ss[0] = a; ss2[0] = a2; }
    }
    __syncthreads();
    float mu  = ss[0]  * (1.0f/NEMBD);
    float var = ss2[0] * (1.0f/NEMBD) - mu*mu;
    float inv = rsqrtf(var + LN_EPS);
    const float4 wv = ((const float4*)w)[t];
    const float4 bv = ((const float4*)b)[t];
    float4 o4;
    o4.x = rndtf((v.x - mu)*inv*wv.x + bv.x);
    o4.y = rndtf((v.y - mu)*inv*wv.y + bv.y);
    o4.z = rndtf((v.z - mu)*inv*wv.z + bv.z);
    o4.w = rndtf((v.w - mu)*inv*wv.w + bv.w);
    ((float4*)(out + (size_t)row*NEMBD))[t] = o4;
}

// ---------------- tf32 tensor-core GEMM, cp.async pipeline, no inner-loop cvt ----------------
// Inputs A and B must already be tf32-rounded. round_out rounds C for downstream GEMM A use.
template<int BM,int BN,int BK,int WM,int WN,int STAGES>
__global__ void __launch_bounds__(((BM/WM)*(BN/WN))*32, 2)
mma_gemm(const float* __restrict__ A, const float* __restrict__ Bm,
         const float* __restrict__ bias, const float* __restrict__ res,
         float* __restrict__ C,
         int M, int N, int K, int lda, int ldb, int ldc,
         float alpha, int relu, int round_out)
{
    constexpr int WARPS_M = BM/WM;
    constexpr int WARPS_N = BN/WN;
    constexpr int THREADS = WARPS_M*WARPS_N*32;
    constexpr int MT = WM/16;
    constexpr int NT = WN/8;
    constexpr int A_STRIDE = BK + 4;
    constexpr int B_STRIDE = BN + 8;

    constexpr int A_CHUNKS = BM*(BK/4);
    constexpr int B_CHUNKS = BK*(BN/4);
    constexpr int A_ITERS  = A_CHUNKS / THREADS;
    constexpr int B_ITERS  = (B_CHUNKS + THREADS - 1) / THREADS;

    extern __shared__ float smem[];
    float* Asf = smem;
    float* Bsf = smem + (size_t)STAGES*BM*A_STRIDE;

    int tid = threadIdx.x;
    int wid = tid >> 5;
    int lane = tid & 31;
    int grp = lane >> 2;
    int qid = lane & 3;
    int warpRow = wid / WARPS_N;
    int warpCol = wid % WARPS_N;

    int row0 = blockIdx.y * BM;
    int col0 = blockIdx.x * BN;

    uint32_t sA = smem_u32(Asf);
    uint32_t sB = smem_u32(Bsf);

    float acc[MT][NT][4];
    #pragma unroll
    for (int i=0;i<MT;i++)
        #pragma unroll
        for (int j=0;j<NT;j++) {
            acc[i][j][0]=0.f; acc[i][j][1]=0.f; acc[i][j][2]=0.f; acc[i][j][3]=0.f;
        }

    int nIter = K / BK;

    auto issue = [&](int s, int buf) {
        #pragma unroll
        for (int t=0; t<A_ITERS; t++) {
            int ch = tid + t*THREADS;
            int r = ch / (BK/4);
            int c = (ch % (BK/4)) * 4;
            cp_async16(sA + (((buf*BM + r)*A_STRIDE + c) << 2),
                       A + (long long)(row0 + r)*lda + s*BK + c);
        }
        #pragma unroll
        for (int t=0; t<B_ITERS; t++) {
            int ch = tid + t*THREADS;
            if (B_CHUNKS % THREADS == 0 || ch < B_CHUNKS) {
                int r = ch / (BN/4);
                int c = (ch % (BN/4)) * 4;
                cp_async16(sB + (((buf*BK + r)*B_STRIDE + c) << 2),
                           Bm + (long long)(s*BK + r)*ldb + col0 + c);
            }
        }
    };

    #pragma unroll
    for (int s=0; s<STAGES-1; s++) {
        if (s < nIter) issue(s, s);
        cp_commit();
    }

    for (int it = 0; it < nIter; it++) {
        cp_wait<STAGES-2>();
        __syncthreads();

        int cur = it % STAGES;
        int nx = it + STAGES - 1;
        if (nx < nIter) issue(nx, nx % STAGES);
        cp_commit();

        const uint32_t* Acur = (const uint32_t*)(Asf + (size_t)cur*BM*A_STRIDE);
        const uint32_t* Bcur = (const uint32_t*)(Bsf + (size_t)cur*BK*B_STRIDE);

        #pragma unroll
        for (int ks = 0; ks < BK/8; ks++) {
            int kb = ks*8;
            uint32_t af[MT][4];
            uint32_t bf[NT][2];
            #pragma unroll
            for (int mt=0; mt<MT; mt++) {
                int r = warpRow*WM + mt*16 + grp;
                af[mt][0] = Acur[(r  )*A_STRIDE + kb + qid    ];
                af[mt][1] = Acur[(r+8)*A_STRIDE + kb + qid    ];
                af[mt][2] = Acur[(r  )*A_STRIDE + kb + qid + 4];
                af[mt][3] = Acur[(r+8)*A_STRIDE + kb + qid + 4];
            }
            #pragma unroll
            for (int nt=0; nt<NT; nt++) {
                int c = warpCol*WN + nt*8 + grp;
                bf[nt][0] = Bcur[(kb + qid    )*B_STRIDE + c];
                bf[nt][1] = Bcur[(kb + qid + 4)*B_STRIDE + c];
            }
            #pragma unroll
            for (int mt=0; mt<MT; mt++)
                #pragma unroll
                for (int nt=0; nt<NT; nt++)
                    mma_tf32(acc[mt][nt], af[mt], bf[nt]);
        }
        __syncthreads();
    }

    #pragma unroll
    for (int mt=0; mt<MT; mt++) {
        int rA = row0 + warpRow*WM + mt*16 + grp;
        int rB = rA + 8;
        #pragma unroll
        for (int nt=0; nt<NT; nt++) {
            int c = col0 + warpCol*WN + nt*8 + qid*2;
            float v0 = acc[mt][nt][0]*alpha;
            float v1 = acc[mt][nt][1]*alpha;
            float v2 = acc[mt][nt][2]*alpha;
            float v3 = acc[mt][nt][3]*alpha;
            if (bias) {
                float2 bb2 = *(const float2*)(bias + c);
                v0 += bb2.x; v1 += bb2.y; v2 += bb2.x; v3 += bb2.y;
            }
            if (relu) {
                v0 = fmaxf(v0,0.f); v1 = fmaxf(v1,0.f);
                v2 = fmaxf(v2,0.f); v3 = fmaxf(v3,0.f);
            }
            if (res) {
                float2 rA2 = *(const float2*)(res + (long long)rA*ldc + c);
                float2 rB2 = *(const float2*)(res + (long long)rB*ldc + c);
                v0 += rA2.x; v1 += rA2.y; v2 += rB2.x; v3 += rB2.y;
            }
            if (round_out) {
                v0 = rndtf(v0); v1 = rndtf(v1); v2 = rndtf(v2); v3 = rndtf(v3);
            }
            *(float2*)(C + (long long)rA*ldc + c) = make_float2(v0, v1);
            *(float2*)(C + (long long)rB*ldc + c) = make_float2(v2, v3);
        }
    }
}

// ---------------- fused flash attention (tf32 mma), causal ----------------
// grid: (SEQ/128, BATCH*NHEAD), block 256 (8 warps x 16 Q-rows).
// q,k,v already tf32-rounded. attn output tf32-rounded (feeds proj GEMM A).
#define QT_S 136
#define KT_S 72
#define VS_S 72
#define PS_S 72
#define FA_SMEM ((64*QT_S + 64*KT_S + 64*VS_S + 128*PS_S)*4)   // 108544 B

__global__ void __launch_bounds__(256, 1)
flash_kernel(const float* __restrict__ q, const float* __restrict__ k,
             const float* __restrict__ v, float* __restrict__ attn)
{
    extern __shared__ float fs[];
    float* Qt = fs;                       // [64][QT_S]  (d, row)
    float* Kt = Qt + 64*QT_S;             // [64][KT_S]  (d, s)
    float* Vs = Kt + 64*KT_S;             // [64][VS_S]  (s, d)
    float* Ps = Vs + 64*VS_S;             // [128][PS_S] (row, s)

    int q0 = blockIdx.x * 128;
    int bh = blockIdx.y;
    int b = bh >> 4, h = bh & 15;
    const float* Qg = q + (long long)b*SEQ*NEMBD + h*HSZ;
    const float* Kg = k + (long long)b*SEQ*NEMBD + h*HSZ;
    const float* Vg = v + (long long)b*SEQ*NEMBD + h*HSZ;

    int tid = threadIdx.x;
    int wid = tid >> 5;
    int lane = tid & 31;
    int grp = lane >> 2;
    int qid = lane & 3;
    int w16 = wid * 16;

    // load Q (transposed into Qt[d][r]); conflict-free STS: lanes vary r
    {
        int r  = tid & 127;
        int cb = (tid >> 7) * 4;
        #pragma unroll
        for (int p = 0; p < 8; p++) {
            int c4 = cb + p*8;
            float4 vv = *(const float4*)(Qg + (long long)(q0 + r)*NEMBD + c4);
            Qt[(c4+0)*QT_S + r] = vv.x;
            Qt[(c4+1)*QT_S + r] = vv.y;
            Qt[(c4+2)*QT_S + r] = vv.z;
            Qt[(c4+3)*QT_S + r] = vv.w;
        }
    }

    float m0 = -INFINITY, m1 = -INFINITY, l0 = 0.f, l1 = 0.f;
    float O[8][4];
    #pragma unroll
    for (int nt=0; nt<8; nt++) { O[nt][0]=0.f; O[nt][1]=0.f; O[nt][2]=0.f; O[nt][3]=0.f; }

    int t0 = q0 + w16 + grp;
    int t1 = t0 + 8;
    int nkv = q0/64 + 2;

    for (int kj = 0; kj < nkv; kj++) {
        int s0 = kj * 64;
        __syncthreads();   // previous iter's PV done before overwriting K/V

        // load K transposed: Kt[d][s]
        {
            int r  = tid & 63;
            int cb = (tid >> 6) * 4;
            #pragma unroll
            for (int p = 0; p < 4; p++) {
                int c4 = cb + p*16;
                float4 vv = *(const float4*)(Kg + (long long)(s0 + r)*NEMBD + c4);
                Kt[(c4+0)*KT_S + r] = vv.x;
                Kt[(c4+1)*KT_S + r] = vv.y;
                Kt[(c4+2)*KT_S + r] = vv.z;
                Kt[(c4+3)*KT_S + r] = vv.w;
            }
        }
        // load V row-major: Vs[s][d]
        for (int ch = tid; ch < 64*16; ch += 256) {
            int r = ch >> 4, c4 = (ch & 15) << 2;
            float4 vv = *(const float4*)(Vg + (long long)(s0 + r)*NEMBD + c4);
            *(float4*)&Vs[r*VS_S + c4] = vv;
        }
        __syncthreads();

        // ---- S = Q K^T (warp: 16x64) ----
        float sacc[8][4];
        #pragma unroll
        for (int nt=0; nt<8; nt++) { sacc[nt][0]=0.f; sacc[nt][1]=0.f; sacc[nt][2]=0.f; sacc[nt][3]=0.f; }

        const uint32_t* Qtu = (const uint32_t*)Qt;
        const uint32_t* Ktu = (const uint32_t*)Kt;
        #pragma unroll
        for (int ks = 0; ks < 8; ks++) {
            int kb = ks*8;
            uint32_t a[4];
            a[0] = Qtu[(kb+qid  )*QT_S + w16 + grp    ];
            a[1] = Qtu[(kb+qid  )*QT_S + w16 + grp + 8];
            a[2] = Qtu[(kb+qid+4)*QT_S + w16 + grp    ];
            a[3] = Qtu[(kb+qid+4)*QT_S + w16 + grp + 8];
            #pragma unroll
            for (int nt=0; nt<8; nt++) {
                uint32_t bb[2];
                bb[0] = Ktu[(kb+qid  )*KT_S + nt*8 + grp];
                bb[1] = Ktu[(kb+qid+4)*KT_S + nt*8 + grp];
                mma_tf32(sacc[nt], a, bb);
            }
        }

        // ---- mask + scale ----
        #pragma unroll
        for (int nt=0; nt<8; nt++) {
            int c = s0 + nt*8 + 2*qid;
            sacc[nt][0] = (c   <= t0) ? sacc[nt][0]*ATT_SCALE : -INFINITY;
            sacc[nt][1] = (c+1 <= t0) ? sacc[nt][1]*ATT_SCALE : -INFINITY;
            sacc[nt][2] = (c   <= t1) ? sacc[nt][2]*ATT_SCALE : -INFINITY;
            sacc[nt][3] = (c+1 <= t1) ? sacc[nt][3]*ATT_SCALE : -INFINITY;
        }

        // ---- row max (across qid quad) ----
        float ml0 = -INFINITY, ml1 = -INFINITY;
        #pragma unroll
        for (int nt=0; nt<8; nt++) {
            ml0 = fmaxf(ml0, fmaxf(sacc[nt][0], sacc[nt][1]));
            ml1 = fmaxf(ml1, fmaxf(sacc[nt][2], sacc[nt][3]));
        }
        ml0 = fmaxf(ml0, __shfl_xor_sync(0xffffffffu, ml0, 1));
        ml0 = fmaxf(ml0, __shfl_xor_sync(0xffffffffu, ml0, 2));
        ml1 = fmaxf(ml1, __shfl_xor_sync(0xffffffffu, ml1, 1));
        ml1 = fmaxf(ml1, __shfl_xor_sync(0xffffffffu, ml1, 2));

        float mn0 = fmaxf(m0, ml0);
        float mn1 = fmaxf(m1, ml1);
        float al0 = __expf(m0 - mn0);
        float al1 = __expf(m1 - mn1);

        // ---- P = exp(S - m), store to Ps (tf32-rounded), row sums ----
        float sum0 = 0.f, sum1 = 0.f;
        #pragma unroll
        for (int nt=0; nt<8; nt++) {
            float p00 = __expf(sacc[nt][0] - mn0);
            float p01 = __expf(sacc[nt][1] - mn0);
            float p10 = __expf(sacc[nt][2] - mn1);
            float p11 = __expf(sacc[nt][3] - mn1);
            sum0 += p00 + p01;
            sum1 += p10 + p11;
            *(float2*)&Ps[(w16+grp  )*PS_S + nt*8 + 2*qid] = make_float2(rndtf(p00), rndtf(p01));
            *(float2*)&Ps[(w16+grp+8)*PS_S + nt*8 + 2*qid] = make_float2(rndtf(p10), rndtf(p11));
        }
        sum0 += __shfl_xor_sync(0xffffffffu, sum0, 1);
        sum0 += __shfl_xor_sync(0xffffffffu, sum0, 2);
        sum1 += __shfl_xor_sync(0xffffffffu, sum1, 1);
        sum1 += __shfl_xor_sync(0xffffffffu, sum1, 2);

        l0 = l0*al0 + sum0;
        l1 = l1*al1 + sum1;
        #pragma unroll
        for (int nt=0; nt<8; nt++) {
            O[nt][0] *= al0; O[nt][1] *= al0;
            O[nt][2] *= al1; O[nt][3] *= al1;
        }
        m0 = mn0; m1 = mn1;
        __syncthreads();   // Ps visible to own warp only actually, but V shared; keep for safety

        // ---- O += P V (warp: 16x64, K=64) ----
        const uint32_t* Psu = (const uint32_t*)Ps;
        const uint32_t* Vsu = (const uint32_t*)Vs;
        #pragma unroll
        for (int ks = 0; ks < 8; ks++) {
            int kb = ks*8;
            uint32_t a[4];
            a[0] = Psu[(w16+grp  )*PS_S + kb + qid    ];
            a[1] = Psu[(w16+grp+8)*PS_S + kb + qid    ];
            a[2] = Psu[(w16+grp  )*PS_S + kb + qid + 4];
            a[3] = Psu[(w16+grp+8)*PS_S + kb + qid + 4];
            #pragma unroll
            for (int nt=0; nt<8; nt++) {
                uint32_t bb[2];
                bb[0] = Vsu[(kb+qid  )*VS_S + nt*8 + grp];
                bb[1] = Vsu[(kb+qid+4)*VS_S + nt*8 + grp];
                mma_tf32(O[nt], a, bb);
            }
        }
    }

    // ---- finalize: O /= l, write (tf32-rounded, feeds proj GEMM A) ----
    float inv0 = 1.0f / l0;
    float inv1 = 1.0f / l1;
    float* outA = attn + ((long long)(b*SEQ + t0))*NEMBD + h*HSZ;
    float* outB = attn + ((long long)(b*SEQ + t1))*NEMBD + h*HSZ;
    #pragma unroll
    for (int nt=0; nt<8; nt++) {
        int c = nt*8 + 2*qid;
        *(float2*)(outA + c) = make_float2(rndtf(O[nt][0]*inv0), rndtf(O[nt][1]*inv0));
        *(float2*)(outB + c) = make_float2(rndtf(O[nt][2]*inv1), rndtf(O[nt][3]*inv1));
    }
}

// ---------------- launch ----------------
extern "C" void kernel_launch(void* const* d_in, const int* in_sizes, int n_in,
                              void* d_out, int out_size)
{
    const float* x     = (const float*)d_in[0];
    const float* Wq    = (const float*)d_in[1];
    const float* Wk    = (const float*)d_in[2];
    const float* Wv    = (const float*)d_in[3];
    const float* Wproj = (const float*)d_in[4];
    const float* bproj = (const float*)d_in[5];
    const float* W1    = (const float*)d_in[6];
    const float* b1    = (const float*)d_in[7];
    const float* W2    = (const float*)d_in[8];
    const float* b2    = (const float*)d_in[9];
    const float* ln1w  = (const float*)d_in[10];
    const float* ln1b  = (const float*)d_in[11];
    const float* ln2w  = (const float*)d_in[12];
    const float* ln2b  = (const float*)d_in[13];
    float* out = (float*)d_out;

    float *ph, *pq, *pk, *pv, *pattn, *px2, *pf1, *pwr;
    cudaGetSymbolAddress((void**)&ph,    g_h);
    cudaGetSymbolAddress((void**)&pq,    g_q);
    cudaGetSymbolAddress((void**)&pk,    g_k);
    cudaGetSymbolAddress((void**)&pv,    g_v);
    cudaGetSymbolAddress((void**)&pattn, g_attn);
    cudaGetSymbolAddress((void**)&px2,   g_x2);
    cudaGetSymbolAddress((void**)&pf1,   g_f1);
    cudaGetSymbolAddress((void**)&pwr,   g_wr);

    const size_t M1 = (size_t)1024*1024;
    float* Wqr = pwr;
    float* Wkr = pwr + M1;
    float* Wvr = pwr + 2*M1;
    float* Wpr = pwr + 3*M1;
    float* W1r = pwr + 4*M1;
    float* W2r = pwr + 8*M1;

    constexpr int ST = 4;
    constexpr size_t SMEM_G128 = (size_t)(ST*128*(16+4) + ST*16*(128+8)) * 4;

    auto* kern128 = mma_gemm<128,128,16,64,32,ST>;
    cudaFuncSetAttribute(kern128, cudaFuncAttributeMaxDynamicSharedMemorySize, (int)SMEM_G128);
    cudaFuncSetAttribute(flash_kernel, cudaFuncAttributeMaxDynamicSharedMemorySize, FA_SMEM);

    // 0) round weights to tf32 once per replay
    {
        int n4a = (int)(M1/4);        // 1M floats -> 256K float4
        int n4b = (int)(4*M1/4);
        round_w_kernel<<<(n4a+255)/256, 256>>>(Wq,    Wqr, n4a);
        round_w_kernel<<<(n4a+255)/256, 256>>>(Wk,    Wkr, n4a);
        round_w_kernel<<<(n4a+255)/256, 256>>>(Wv,    Wvr, n4a);
        round_w_kernel<<<(n4a+255)/256, 256>>>(Wproj, Wpr, n4a);
        round_w_kernel<<<(n4b+255)/256, 256>>>(W1,    W1r, n4b);
        round_w_kernel<<<(n4b+255)/256, 256>>>(W2,    W2r, n4b);
    }

    // 1) LN1 (output tf32-rounded)
    ln_kernel<<<BT, 256>>>(x, ln1w, ln1b, ph);

    // 2) Q,K,V projections (outputs tf32-rounded for flash)
    {
        dim3 grid(NEMBD/128, BT/128);
        kern128<<<grid, 256, SMEM_G128>>>(ph, Wqr, nullptr, nullptr, pq,
            BT, NEMBD, NEMBD, NEMBD, NEMBD, NEMBD, 1.0f, 0, 1);
        kern128<<<grid, 256, SMEM_G128>>>(ph, Wkr, nullptr, nullptr, pk,
            BT, NEMBD, NEMBD, NEMBD, NEMBD, NEMBD, 1.0f, 0, 1);
        kern128<<<grid, 256, SMEM_G128>>>(ph, Wvr, nullptr, nullptr, pv,
            BT, NEMBD, NEMBD, NEMBD, NEMBD, NEMBD, 1.0f, 0, 1);
    }

    // 3) fused flash attention -> g_attn (tf32-rounded)
    {
        dim3 grid(SEQ/128, BATCH*NHEAD);
        flash_kernel<<<grid, 256, FA_SMEM>>>(pq, pk, pv, pattn);
    }

    // 4) x2 = x + attn @ Wproj + bproj
    {
        dim3 grid(NEMBD/128, BT/128);
        kern128<<<grid, 256, SMEM_G128>>>(pattn, Wpr, bproj, x, px2,
            BT, NEMBD, NEMBD, NEMBD, NEMBD, NEMBD, 1.0f, 0, 0);
    }

    // 5) LN2 (output tf32-rounded)
    ln_kernel<<<BT, 256>>>(px2, ln2w, ln2b, ph);

    // 6) f1 = relu(h2 @ W1 + b1), output tf32-rounded
    {
        dim3 grid(FFDIM/128, BT/128);
        kern128<<<grid, 256, SMEM_G128>>>(ph, W1r, b1, nullptr, pf1,
            BT, FFDIM, NEMBD, NEMBD, FFDIM, FFDIM, 1.0f, 1, 1);
    }

    // 7) out = x2 + f1 @ W2 + b2
    {
        dim3 grid(NEMBD/128, BT/128);
        kern128<<<grid, 256, SMEM_G128>>>(pf1, W2r, b2, px2, out,
            BT, NEMBD, FFDIM, FFDIM, NEMBD, NEMBD, 1.0f, 0, 0);
    }
}